// round 9
// baseline (speedup 1.0000x reference)
#include <cuda_runtime.h>
#include <cuda_bf16.h>
#include <stdint.h>

// ---------------------------------------------------------------------------
// out = relu(relu(conv3x3(x) @ w1 + b1) @ w2 + b2) @ w3 + b3 , B=65536
// conv folded into FC1 (W_eff). GEMMs via mma.sync m16n8k16 bf16 (base-target
// PTX — tcgen05 is rejected by this build's compute_103 virtual arch).
// fp32 accuracy recovered with hi/lo bf16 x3 split: ah*bh + al*bh + ah*bl.
// ---------------------------------------------------------------------------

#define CTA_M    128
#define NTHREADS 512

// prep scratch: W_eff^T (conv folded into w1), w2^T — bf16 hi/lo row-major
__device__ __align__(16) __nv_bfloat16 g_w1T_hi[256 * 832];
__device__ __align__(16) __nv_bfloat16 g_w1T_lo[256 * 832];
__device__ __align__(16) __nv_bfloat16 g_w2T_hi[128 * 256];
__device__ __align__(16) __nv_bfloat16 g_w2T_lo[128 * 256];

// ---- smem layout (bytes, dynamic) ----
#define SM_B1   0                   // 256 f32
#define SM_B2   1024                // 128 f32
#define SM_B3   1536                // 16 f32
#define SM_W3   1600                // 1280 f32 (w3 raw [128][10])
#define SM_MAIN 6720
// layer-1 staging (per 64-k chunk)
#define L1_AHI  (SM_MAIN)           // [128 m][72 k] bf16, stride 144 B
#define L1_ALO  (SM_MAIN + 18432)
#define L1_BHI  (SM_MAIN + 36864)   // [256 n][72 k] bf16
#define L1_BLO  (SM_MAIN + 73728)   // end MAIN+110592
// layer-2: h1 full + w2T chunk
#define H1_HI   (SM_MAIN)           // [128 m][264 k] bf16, stride 528 B
#define H1_LO   (SM_MAIN + 67584)   // end MAIN+135168
#define L2_BHI  (SM_MAIN + 135168)  // [128 n][72 k] bf16
#define L2_BLO  (SM_MAIN + 153600)  // end MAIN+172032
// layer-3: h2 fp32 over h1 area
#define H2_F32  (SM_MAIN)           // [128 m][132 k] f32, stride 528 B
#define SMEM_SZ 178752

// ---------------------------------------------------------------------------
__device__ __forceinline__ uint32_t s2u(const void* p) {
    uint32_t a;
    asm("{ .reg .u64 t; cvta.to.shared.u64 t, %1; cvt.u32.u64 %0, t; }"
        : "=r"(a) : "l"(p));
    return a;
}

__device__ __forceinline__ void ldmx4(uint32_t* r, uint32_t addr) {
    asm volatile("ldmatrix.sync.aligned.m8n8.x4.shared.b16 {%0,%1,%2,%3}, [%4];"
                 : "=r"(r[0]), "=r"(r[1]), "=r"(r[2]), "=r"(r[3]) : "r"(addr));
}
__device__ __forceinline__ void ldmx2(uint32_t* r, uint32_t addr) {
    asm volatile("ldmatrix.sync.aligned.m8n8.x2.shared.b16 {%0,%1}, [%2];"
                 : "=r"(r[0]), "=r"(r[1]) : "r"(addr));
}
__device__ __forceinline__ void mma16816(float* c, const uint32_t* a,
                                         const uint32_t* b) {
    asm volatile(
        "mma.sync.aligned.m16n8k16.row.col.f32.bf16.bf16.f32 "
        "{%0,%1,%2,%3}, {%4,%5,%6,%7}, {%8,%9}, {%0,%1,%2,%3};"
        : "+f"(c[0]), "+f"(c[1]), "+f"(c[2]), "+f"(c[3])
        : "r"(a[0]), "r"(a[1]), "r"(a[2]), "r"(a[3]), "r"(b[0]), "r"(b[1]));
}

__device__ __forceinline__ uint32_t pk(__nv_bfloat16 a, __nv_bfloat16 b) {
    unsigned short ra = *(unsigned short*)&a, rb = *(unsigned short*)&b;
    return (uint32_t)ra | ((uint32_t)rb << 16);
}
// split two f32 into packed bf16-hi pair and bf16-lo pair
__device__ __forceinline__ void split2(float v0, float v1,
                                       uint32_t& hi, uint32_t& lo) {
    __nv_bfloat16 h0 = __float2bfloat16(v0);
    __nv_bfloat16 h1 = __float2bfloat16(v1);
    __nv_bfloat16 l0 = __float2bfloat16(v0 - __bfloat162float(h0));
    __nv_bfloat16 l1 = __float2bfloat16(v1 - __bfloat162float(h1));
    hi = pk(h0, h1);
    lo = pk(l0, l1);
}

// ---------------------------------------------------------------------------
// prep: W_eff^T[n][p] = sum_{dr,dc} conv_w[dr,dc] * w1[(rr*26+cc)*256+n]
// ---------------------------------------------------------------------------
__global__ void prep_w1T(const float* __restrict__ cw,
                         const float* __restrict__ w1) {
    int idx = blockIdx.x * 256 + threadIdx.x;   // 832 blocks -> 256*832 elems
    int n = idx / 832, p = idx % 832;
    float acc = 0.f;
    if (p < 784) {
        int r = p / 28, c = p % 28;
#pragma unroll
        for (int dr = 0; dr < 3; dr++)
#pragma unroll
            for (int dc = 0; dc < 3; dc++) {
                int rr = r - dr, cc = c - dc;
                if (rr >= 0 && rr < 26 && cc >= 0 && cc < 26)
                    acc += cw[dr * 3 + dc] * w1[(rr * 26 + cc) * 256 + n];
            }
    }
    __nv_bfloat16 h = __float2bfloat16(acc);
    __nv_bfloat16 l = __float2bfloat16(acc - __bfloat162float(h));
    g_w1T_hi[n * 832 + p] = h;
    g_w1T_lo[n * 832 + p] = l;
}

__global__ void prep_w2T(const float* __restrict__ w2) {
    int idx = blockIdx.x * 256 + threadIdx.x;   // 128 blocks -> 128*256
    int n = idx / 256, k = idx % 256;
    float v = w2[k * 128 + n];
    __nv_bfloat16 h = __float2bfloat16(v);
    __nv_bfloat16 l = __float2bfloat16(v - __bfloat162float(h));
    g_w2T_hi[n * 256 + k] = h;
    g_w2T_lo[n * 256 + k] = l;
}

// ---------------------------------------------------------------------------
// fused MLP: 1 CTA = 128 batch rows, 512 threads = 16 warps
// ---------------------------------------------------------------------------
__global__ void __launch_bounds__(NTHREADS, 1)
fused_mlp(const float* __restrict__ x, const float* __restrict__ b1g,
          const float* __restrict__ b2g, const float* __restrict__ b3g,
          const float* __restrict__ w3g, float* __restrict__ out) {
    extern __shared__ unsigned char smem[];
    const uint32_t sb = s2u(smem);
    const int tid = threadIdx.x;
    const int lane = tid & 31;
    const int wid = tid >> 5;
    const int wm = wid >> 2;        // 0..3 -> rows 32*wm
    const int wn = wid & 3;         // 0..3
    const int g = lane >> 2;        // mma group id
    const int t4 = lane & 3;

    float* b1s = (float*)(smem + SM_B1);
    float* b2s = (float*)(smem + SM_B2);
    float* b3s = (float*)(smem + SM_B3);
    float* w3s = (float*)(smem + SM_W3);
    for (int i = tid; i < 256; i += NTHREADS) b1s[i] = b1g[i];
    if (tid < 128) b2s[tid] = b2g[tid];
    if (tid < 16)  b3s[tid] = (tid < 10) ? b3g[tid] : 0.f;
    for (int i = tid; i < 1280; i += NTHREADS) w3s[i] = w3g[i];

    const float* xblk = x + (size_t)blockIdx.x * CTA_M * 784;

    // ---------------- layer 1: [128,832] x [832,256] -----------------------
    float c1[2][8][4];
#pragma unroll
    for (int a = 0; a < 2; a++)
#pragma unroll
        for (int b = 0; b < 8; b++)
#pragma unroll
            for (int c = 0; c < 4; c++) c1[a][b][c] = 0.f;

    for (int cc = 0; cc < 13; cc++) {
        __syncthreads();   // previous chunk fully consumed (also covers bias)
        // A: x chunk [128][64] fp32 -> bf16 hi/lo, rows padded to 144 B
#pragma unroll
        for (int j = 0; j < 4; j++) {
            int idx = tid + NTHREADS * j;        // 0..2047
            int row = idx >> 4, f4 = idx & 15;
            float4 v = make_float4(0.f, 0.f, 0.f, 0.f);
            if (cc < 12 || f4 < 4)
                v = *(const float4*)(xblk + (size_t)row * 784 + cc * 64 + f4 * 4);
            uint32_t h0, l0, h1, l1;
            split2(v.x, v.y, h0, l0);
            split2(v.z, v.w, h1, l1);
            uint32_t off = row * 144 + f4 * 8;
            *(uint2*)(smem + L1_AHI + off) = make_uint2(h0, h1);
            *(uint2*)(smem + L1_ALO + off) = make_uint2(l0, l1);
        }
        // B: w1T chunk [256][64] hi/lo (pre-split, just copy)
#pragma unroll
        for (int j = 0; j < 4; j++) {
            int idx = tid + NTHREADS * j;        // 0..2047 uint4s
            int n = idx >> 3, kq = idx & 7;
            const uint4* sh = (const uint4*)(g_w1T_hi + n * 832 + cc * 64) + kq;
            const uint4* sl = (const uint4*)(g_w1T_lo + n * 832 + cc * 64) + kq;
            uint32_t off = n * 144 + kq * 16;
            *(uint4*)(smem + L1_BHI + off) = *sh;
            *(uint4*)(smem + L1_BLO + off) = *sl;
        }
        __syncthreads();

#pragma unroll
        for (int ks = 0; ks < 4; ks++) {
            uint32_t ah[2][4], al[2][4];
#pragma unroll
            for (int mf = 0; mf < 2; mf++) {
                uint32_t aaddr = sb + L1_AHI +
                    (32 * wm + mf * 16 + (lane & 15)) * 144 +
                    ks * 32 + ((lane >> 4) << 4);
                ldmx4(ah[mf], aaddr);
                ldmx4(al[mf], aaddr + (L1_ALO - L1_AHI));
            }
#pragma unroll
            for (int j = 0; j < 8; j++) {
                int n0 = 64 * wn + 8 * j;
                uint32_t baddr = sb + L1_BHI + (n0 + (lane & 7)) * 144 +
                    ks * 32 + (((lane >> 3) & 1) << 4);
                uint32_t bh[2], bl[2];
                ldmx2(bh, baddr);
                ldmx2(bl, baddr + (L1_BLO - L1_BHI));
#pragma unroll
                for (int mf = 0; mf < 2; mf++) {
                    mma16816(c1[mf][j], ah[mf], bh);
                    mma16816(c1[mf][j], al[mf], bh);
                    mma16816(c1[mf][j], ah[mf], bl);
                }
            }
        }
    }

    // L1 epilogue: h1 = relu(c1+b1) -> smem bf16 hi/lo [128][264]
    __syncthreads();   // all warps done reading L1 tiles before overwrite
#pragma unroll
    for (int mf = 0; mf < 2; mf++)
#pragma unroll
        for (int j = 0; j < 8; j++)
#pragma unroll
            for (int ci = 0; ci < 4; ci += 2) {
                int row = 32 * wm + mf * 16 + g + (ci ? 8 : 0);
                int col = 64 * wn + 8 * j + 2 * t4;
                float v0 = fmaxf(c1[mf][j][ci]     + b1s[col],     0.f);
                float v1 = fmaxf(c1[mf][j][ci + 1] + b1s[col + 1], 0.f);
                uint32_t hi, lo;
                split2(v0, v1, hi, lo);
                uint32_t off = row * 528 + col * 2;
                *(uint32_t*)(smem + H1_HI + off) = hi;
                *(uint32_t*)(smem + H1_LO + off) = lo;
            }
    __syncthreads();

    // ---------------- layer 2: [128,256] x [256,128] -----------------------
    float c2[2][4][4];
#pragma unroll
    for (int a = 0; a < 2; a++)
#pragma unroll
        for (int b = 0; b < 4; b++)
#pragma unroll
            for (int c = 0; c < 4; c++) c2[a][b][c] = 0.f;

    for (int ch = 0; ch < 4; ch++) {
        if (ch) __syncthreads();
#pragma unroll
        for (int j = 0; j < 2; j++) {
            int idx = tid + NTHREADS * j;        // 0..1023 uint4s
            int n = idx >> 3, kq = idx & 7;
            const uint4* sh = (const uint4*)(g_w2T_hi + n * 256 + ch * 64) + kq;
            const uint4* sl = (const uint4*)(g_w2T_lo + n * 256 + ch * 64) + kq;
            uint32_t off = n * 144 + kq * 16;
            *(uint4*)(smem + L2_BHI + off) = *sh;
            *(uint4*)(smem + L2_BLO + off) = *sl;
        }
        __syncthreads();

#pragma unroll
        for (int ks = 0; ks < 4; ks++) {
            uint32_t ah[2][4], al[2][4];
#pragma unroll
            for (int mf = 0; mf < 2; mf++) {
                uint32_t aaddr = sb + H1_HI +
                    (32 * wm + mf * 16 + (lane & 15)) * 528 +
                    ch * 128 + ks * 32 + ((lane >> 4) << 4);
                ldmx4(ah[mf], aaddr);
                ldmx4(al[mf], aaddr + (H1_LO - H1_HI));
            }
#pragma unroll
            for (int j = 0; j < 4; j++) {
                int n0 = 32 * wn + 8 * j;
                uint32_t baddr = sb + L2_BHI + (n0 + (lane & 7)) * 144 +
                    ks * 32 + (((lane >> 3) & 1) << 4);
                uint32_t bh[2], bl[2];
                ldmx2(bh, baddr);
                ldmx2(bl, baddr + (L2_BLO - L2_BHI));
#pragma unroll
                for (int mf = 0; mf < 2; mf++) {
                    mma16816(c2[mf][j], ah[mf], bh);
                    mma16816(c2[mf][j], al[mf], bh);
                    mma16816(c2[mf][j], ah[mf], bl);
                }
            }
        }
    }

    // L2 epilogue: h2 = relu(c2+b2) fp32 -> smem [128][132] (over h1)
    __syncthreads();
    float* h2f = (float*)(smem + H2_F32);
#pragma unroll
    for (int mf = 0; mf < 2; mf++)
#pragma unroll
        for (int j = 0; j < 4; j++)
#pragma unroll
            for (int ci = 0; ci < 4; ci += 2) {
                int row = 32 * wm + mf * 16 + g + (ci ? 8 : 0);
                int col = 32 * wn + 8 * j + 2 * t4;
                h2f[row * 132 + col]     = fmaxf(c2[mf][j][ci]     + b2s[col],     0.f);
                h2f[row * 132 + col + 1] = fmaxf(c2[mf][j][ci + 1] + b2s[col + 1], 0.f);
            }
    __syncthreads();

    // ---------------- layer 3: [128,128] x [128,10], exact fp32 ------------
    for (int it = tid; it < 1280; it += NTHREADS) {
        int row = it / 10, col = it - row * 10;
        float acc = b3s[col];
        const float* hr = h2f + row * 132;
#pragma unroll 8
        for (int k = 0; k < 128; k++)
            acc = fmaf(hr[k], w3s[k * 10 + col], acc);
        out[((size_t)blockIdx.x * CTA_M + row) * 10 + col] = acc;
    }
}

// ---------------------------------------------------------------------------
extern "C" void kernel_launch(void* const* d_in, const int* in_sizes, int n_in,
                              void* d_out, int out_size) {
    const float* x  = (const float*)d_in[0];
    const float* cw = (const float*)d_in[1];
    const float* w1 = (const float*)d_in[2];
    const float* b1 = (const float*)d_in[3];
    const float* w2 = (const float*)d_in[4];
    const float* b2 = (const float*)d_in[5];
    const float* w3 = (const float*)d_in[6];
    const float* b3 = (const float*)d_in[7];
    (void)in_sizes; (void)n_in; (void)out_size;

    prep_w1T<<<832, 256>>>(cw, w1);
    prep_w2T<<<128, 256>>>(w2);

    static int cfg_done = 0;
    if (!cfg_done) {
        cudaFuncSetAttribute(fused_mlp,
                             cudaFuncAttributeMaxDynamicSharedMemorySize,
                             SMEM_SZ);
        cfg_done = 1;
    }
    fused_mlp<<<512, NTHREADS, SMEM_SZ>>>(x, b1, b2, b3, w3, (float*)d_out);
}